// round 6
// baseline (speedup 1.0000x reference)
#include <cuda_runtime.h>
#include <cstdint>

#define BATCH 64
#define HH 512
#define WW 512
#define TILE_H 32
#define TILE_W 256
#define NROWT (HH / TILE_H)          // 16
#define NCOLT (WW / TILE_W)          // 2
#define NPART (BATCH * NROWT * NCOLT) // 2048
#define NTHREADS 128
#define DEPTH 8
#define DIST 6
#define ROWF 272                     // 8 halo + 256 + 8 halo floats
#define NSTAGE (TILE_H + 10)         // 42 staged rows per tile

typedef unsigned long long u64;

__device__ float g_partials[NPART];
__device__ unsigned int g_ticket = 0;

// ---- packed f32x2 helpers (Blackwell FFMA2 path, PTX-only) ----
__device__ __forceinline__ u64 pk2(float lo, float hi) {
    u64 r; asm("mov.b64 %0, {%1, %2};" : "=l"(r) : "f"(lo), "f"(hi)); return r;
}
__device__ __forceinline__ void upk2(u64 v, float& lo, float& hi) {
    asm("mov.b64 {%0, %1}, %2;" : "=f"(lo), "=f"(hi) : "l"(v));
}
__device__ __forceinline__ u64 f2mul(u64 a, u64 b) {
    u64 d; asm("mul.rn.f32x2 %0, %1, %2;" : "=l"(d) : "l"(a), "l"(b)); return d;
}
__device__ __forceinline__ u64 f2add(u64 a, u64 b) {
    u64 d; asm("add.rn.f32x2 %0, %1, %2;" : "=l"(d) : "l"(a), "l"(b)); return d;
}
__device__ __forceinline__ u64 f2fma(u64 a, u64 b, u64 c) {
    u64 d; asm("fma.rn.f32x2 %0, %1, %2, %3;" : "=l"(d) : "l"(a), "l"(b), "l"(c)); return d;
}

__global__ __launch_bounds__(NTHREADS, 1)
void ssim_map_kernel(const float* __restrict__ x, const float* __restrict__ y,
                     const float* __restrict__ win, float* __restrict__ out)
{
    __shared__ float sbuf[DEPTH][2][ROWF];   // 17408 B row ring, fields x/y
    __shared__ float swarp[4];
    __shared__ int s_last;

    const int t  = threadIdx.x;
    const int ct = blockIdx.x & 1;           // column tile
    const int rt = blockIdx.x >> 1;          // row tile
    const int b  = blockIdx.y;
    const int c0 = ct * TILE_W;
    const int r0 = rt * TILE_H;
    const float* xb = x + (size_t)b * HH * WW;
    const float* yb = y + (size_t)b * HH * WW;

    // zero column halos once: 8 slots * 2 fields * 8 float2 = 128 = blockDim
    {
        int slot = t >> 4, f = (t >> 3) & 1, k = t & 7;
        int pos = (k < 4) ? 2 * k : (264 + 2 * (k - 4));
        *(float2*)&sbuf[slot][f][pos] = make_float2(0.f, 0.f);
    }

    // recover separable 1D taps: g[i] = sum_j w2d[i][j] (sum g == 1), packed (g,g)
    u64 g2[11];
    #pragma unroll
    for (int i = 0; i < 11; ++i) {
        float s = 0.f;
        #pragma unroll
        for (int j = 0; j < 11; ++j) s += win[i * 11 + j];
        g2[i] = pk2(s, s);
    }

    const u64 HC1  = pk2(5e-5f, 5e-5f);     // C1/2
    const u64 HC2  = pk2(4.5e-4f, 4.5e-4f); // C2/2
    const u64 FC1  = pk2(1e-4f, 1e-4f);     // C1
    const u64 FC2  = pk2(9e-4f, 9e-4f);     // C2
    const u64 NEG1 = pk2(-1.f, -1.f);

    // ---- row fill: cp.async 8B per field; zeros (plain STS) for invalid rows ----
    auto fill_row = [&](int p) {
        int slot = p & 7;
        int r_in = r0 - 5 + p;
        float* bx = sbuf[slot][0];
        float* by = sbuf[slot][1];
        if ((unsigned)r_in < (unsigned)HH) {
            const float* rxg = xb + (size_t)r_in * WW;
            const float* ryg = yb + (size_t)r_in * WW;
            {
                unsigned sx = (unsigned)__cvta_generic_to_shared(&bx[8 + 2 * t]);
                unsigned sy = (unsigned)__cvta_generic_to_shared(&by[8 + 2 * t]);
                const float* gx = rxg + c0 + 2 * t;
                const float* gy = ryg + c0 + 2 * t;
                asm volatile("cp.async.ca.shared.global [%0], [%1], 8;" :: "r"(sx), "l"(gx) : "memory");
                asm volatile("cp.async.ca.shared.global [%0], [%1], 8;" :: "r"(sy), "l"(gy) : "memory");
            }
            if (t < 4) {
                if (c0 > 0) {  // left halo cols c0-8+2t
                    int col = c0 - 8 + 2 * t;
                    unsigned sx = (unsigned)__cvta_generic_to_shared(&bx[2 * t]);
                    unsigned sy = (unsigned)__cvta_generic_to_shared(&by[2 * t]);
                    asm volatile("cp.async.ca.shared.global [%0], [%1], 8;" :: "r"(sx), "l"(rxg + col) : "memory");
                    asm volatile("cp.async.ca.shared.global [%0], [%1], 8;" :: "r"(sy), "l"(ryg + col) : "memory");
                }
            } else if (t < 8) {
                if (c0 + TILE_W < WW) {  // right halo cols c0+256+2(t-4)
                    int k = t - 4;
                    int col = c0 + TILE_W + 2 * k;
                    unsigned sx = (unsigned)__cvta_generic_to_shared(&bx[264 + 2 * k]);
                    unsigned sy = (unsigned)__cvta_generic_to_shared(&by[264 + 2 * k]);
                    asm volatile("cp.async.ca.shared.global [%0], [%1], 8;" :: "r"(sx), "l"(rxg + col) : "memory");
                    asm volatile("cp.async.ca.shared.global [%0], [%1], 8;" :: "r"(sy), "l"(ryg + col) : "memory");
                }
            }
        } else {
            *(float2*)&bx[8 + 2 * t] = make_float2(0.f, 0.f);
            *(float2*)&by[8 + 2 * t] = make_float2(0.f, 0.f);
            if (t < 4) {
                if (c0 > 0) {
                    *(float2*)&bx[2 * t] = make_float2(0.f, 0.f);
                    *(float2*)&by[2 * t] = make_float2(0.f, 0.f);
                }
            } else if (t < 8) {
                if (c0 + TILE_W < WW) {
                    int k = t - 4;
                    *(float2*)&bx[264 + 2 * k] = make_float2(0.f, 0.f);
                    *(float2*)&by[264 + 2 * k] = make_float2(0.f, 0.f);
                }
            }
        }
    };

    // prologue: prefetch rows 0..DIST-1, one commit group each
    #pragma unroll
    for (int p = 0; p < DIST; ++p) {
        fill_row(p);
        asm volatile("cp.async.commit_group;" ::: "memory");
    }

    // register ring: 11 rows x 4 packed fields (mu_x, mu_y, x^2+y^2, x*y)
    u64 RX[11], RY[11], RS[11], RP[11];
    float acc = 0.f;

    for (int blk = 0; blk < 4; ++blk) {
        #pragma unroll
        for (int ph = 0; ph < 11; ++ph) {
            const int pr = blk * 11 + ph;
            if (pr < NSTAGE) {
                // single-sync pipeline: write slot (pr+6)&7 = (pr-2)&7 cannot
                // collide with laggard reads of slot (pr-1)&7; older reads are
                // fenced by the previous iteration's barrier.
                int pf = pr + DIST;
                if (pf < NSTAGE) fill_row(pf);
                asm volatile("cp.async.commit_group;" ::: "memory");
                asm volatile("cp.async.wait_group %0;" :: "n"(DIST) : "memory");
                __syncthreads();                       // row pr visible to all

                // stage 14 floats per field into registers (aligned float2 loads)
                const float2* xv = (const float2*)sbuf[pr & 7][0] + (t + 1);
                const float2* yv = (const float2*)sbuf[pr & 7][1] + (t + 1);
                float xr[14], yr[14];
                #pragma unroll
                for (int i = 0; i < 7; ++i) {
                    float2 a = xv[i]; xr[2 * i] = a.x; xr[2 * i + 1] = a.y;
                    float2 c = yv[i]; yr[2 * i] = c.x; yr[2 * i + 1] = c.y;
                }

                // horizontal 11-tap conv, packed over column pair (2t, 2t+1)
                u64 hx = 0, hy = 0, hs = 0, hp = 0;
                #pragma unroll
                for (int j = 0; j < 11; ++j) {
                    u64 ax = pk2(xr[1 + j], xr[2 + j]);
                    u64 ay = pk2(yr[1 + j], yr[2 + j]);
                    hx = f2fma(g2[j], ax, hx);
                    hy = f2fma(g2[j], ay, hy);
                    u64 ss = f2mul(ax, ax);
                    ss = f2fma(ay, ay, ss);
                    hs = f2fma(g2[j], ss, hs);
                    u64 pp = f2mul(ax, ay);
                    hp = f2fma(g2[j], pp, hp);
                }
                RX[ph] = hx; RY[ph] = hy; RS[ph] = hs; RP[ph] = hp;

                // vertical 11-tap conv + SSIM once ring is warm
                if (pr >= 10) {
                    u64 mx = f2mul(g2[0], RX[(ph + 1) % 11]);
                    u64 my = f2mul(g2[0], RY[(ph + 1) % 11]);
                    u64 sp = f2mul(g2[0], RS[(ph + 1) % 11]);
                    u64 sx = f2mul(g2[0], RP[(ph + 1) % 11]);
                    #pragma unroll
                    for (int k = 1; k < 11; ++k) {
                        const int sl = (ph + 1 + k) % 11;
                        mx = f2fma(g2[k], RX[sl], mx);
                        my = f2fma(g2[k], RY[sl], my);
                        sp = f2fma(g2[k], RS[sl], sp);
                        sx = f2fma(g2[k], RP[sl], sx);
                    }
                    u64 mx2 = f2mul(mx, mx);
                    u64 my2 = f2mul(my, my);
                    u64 mxy = f2mul(mx, my);
                    u64 msq = f2add(mx2, my2);
                    u64 vp  = f2fma(msq, NEG1, sp);    // sigma_x^2 + sigma_y^2
                    u64 vxy = f2fma(mxy, NEG1, sx);    // sigma_xy
                    u64 t1  = f2add(mxy, HC1);
                    u64 t2  = f2add(vxy, HC2);
                    u64 num = f2mul(t1, t2);           // ssim = 4*num/den
                    u64 t3  = f2add(msq, FC1);
                    u64 t4  = f2add(vp,  FC2);
                    u64 den = f2mul(t3, t4);
                    float n0, n1, d0, d1;
                    upk2(num, n0, n1);
                    upk2(den, d0, d1);
                    acc += __fdividef(n0, d0) + __fdividef(n1, d1);
                }
            }
        }
    }

    // ---- deterministic per-CTA reduction -> partial ----
    #pragma unroll
    for (int o = 16; o; o >>= 1) acc += __shfl_down_sync(0xFFFFFFFFu, acc, o);
    __syncthreads();
    if ((t & 31) == 0) swarp[t >> 5] = acc;
    __syncthreads();
    if (t == 0) {
        float s = (swarp[0] + swarp[1]) + (swarp[2] + swarp[3]);
        g_partials[blockIdx.y * 32 + blockIdx.x] = s;
        __threadfence();
        unsigned old = atomicAdd(&g_ticket, 1u);
        s_last = (old == NPART - 1);
    }
    __syncthreads();

    // ---- last CTA: fixed-order final reduction (deterministic) ----
    if (s_last) {
        __threadfence();
        float v = 0.f;
        #pragma unroll
        for (int k = 0; k < NPART / NTHREADS; ++k)
            v += g_partials[t + NTHREADS * k];
        #pragma unroll
        for (int o = 16; o; o >>= 1) v += __shfl_down_sync(0xFFFFFFFFu, v, o);
        __syncthreads();   // reuse swarp safely
        if ((t & 31) == 0) swarp[t >> 5] = v;
        __syncthreads();
        if (t == 0) {
            float s = (swarp[0] + swarp[1]) + (swarp[2] + swarp[3]);
            // accumulated terms were num/4 / den -> scale by 4 / (B*H*W)
            out[0] = s * (4.0f / 16777216.0f);
            g_ticket = 0;   // reset for next graph replay
        }
    }
}

extern "C" void kernel_launch(void* const* d_in, const int* in_sizes, int n_in,
                              void* d_out, int out_size)
{
    const float* x   = (const float*)d_in[0];
    const float* y   = (const float*)d_in[1];
    const float* win = (const float*)d_in[2];
    float* out = (float*)d_out;

    dim3 grid(NROWT * NCOLT, BATCH);   // (32, 64) = 2048 CTAs
    ssim_map_kernel<<<grid, NTHREADS>>>(x, y, win, out);
}

// round 7
// speedup vs baseline: 1.0327x; 1.0327x over previous
#include <cuda_runtime.h>
#include <cstdint>

#define BATCH 64
#define HH 512
#define WW 512
#define TILE_H 64
#define NROWT (HH / TILE_H)            // 8
#define NCOLT 2
#define NPART (BATCH * NROWT * NCOLT)  // 1024
#define NTHREADS 128
#define NWARP 4
#define DEPTH 8
#define DIST 6
#define WROWF 80                        // 8 halo + 64 + 8 halo floats per warp
#define NSTAGE (TILE_H + 10)            // 74 staged rows per tile

typedef unsigned long long u64;

__device__ float g_partials[NPART];
__device__ unsigned int g_ticket = 0;

// ---- packed f32x2 helpers (Blackwell FFMA2 path, PTX-only) ----
__device__ __forceinline__ u64 pk2(float lo, float hi) {
    u64 r; asm("mov.b64 %0, {%1, %2};" : "=l"(r) : "f"(lo), "f"(hi)); return r;
}
__device__ __forceinline__ void upk2(u64 v, float& lo, float& hi) {
    asm("mov.b64 {%0, %1}, %2;" : "=f"(lo), "=f"(hi) : "l"(v));
}
__device__ __forceinline__ u64 f2mul(u64 a, u64 b) {
    u64 d; asm("mul.rn.f32x2 %0, %1, %2;" : "=l"(d) : "l"(a), "l"(b)); return d;
}
__device__ __forceinline__ u64 f2add(u64 a, u64 b) {
    u64 d; asm("add.rn.f32x2 %0, %1, %2;" : "=l"(d) : "l"(a), "l"(b)); return d;
}
__device__ __forceinline__ u64 f2fma(u64 a, u64 b, u64 c) {
    u64 d; asm("fma.rn.f32x2 %0, %1, %2, %3;" : "=l"(d) : "l"(a), "l"(b), "l"(c)); return d;
}

__global__ __launch_bounds__(NTHREADS, 1)
void ssim_map_kernel(const float* __restrict__ x, const float* __restrict__ y,
                     const float* __restrict__ win, float* __restrict__ out)
{
    // warp-private staging: [slot][field][warp][80 floats]  (20480 B)
    __shared__ float sbuf[DEPTH][2][NWARP][WROWF];
    __shared__ float swarp[NWARP];
    __shared__ int s_last;

    const int t  = threadIdx.x;
    const int w  = t >> 5;
    const int tl = t & 31;
    const int ct = blockIdx.x & 1;           // column tile (0/1)
    const int rt = blockIdx.x >> 1;          // row tile (0..7)
    const int b  = blockIdx.y;
    const int cw = ct * 256 + w * 64;        // warp's first output column
    const int r0 = rt * TILE_H;
    const float* xb = x + (size_t)b * HH * WW;
    const float* yb = y + (size_t)b * HH * WW;

    const bool lvalid = (cw > 0);            // left halo cols cw-8..cw-1 in image
    const bool rvalid = (cw + 64 < WW);      // right halo cols cw+64..cw+71 in image

    // zero ONLY always-invalid halo lanes once (never cp.async targets)
    if (!lvalid && tl < 4) {
        #pragma unroll
        for (int s = 0; s < DEPTH; ++s) {
            *(float2*)&sbuf[s][0][w][2 * tl] = make_float2(0.f, 0.f);
            *(float2*)&sbuf[s][1][w][2 * tl] = make_float2(0.f, 0.f);
        }
    }
    if (!rvalid && tl >= 4 && tl < 8) {
        int k = tl - 4;
        #pragma unroll
        for (int s = 0; s < DEPTH; ++s) {
            *(float2*)&sbuf[s][0][w][72 + 2 * k] = make_float2(0.f, 0.f);
            *(float2*)&sbuf[s][1][w][72 + 2 * k] = make_float2(0.f, 0.f);
        }
    }

    // recover separable 1D taps: g[i] = sum_j w2d[i][j] (sum g == 1), packed (g,g)
    u64 g2[11];
    #pragma unroll
    for (int i = 0; i < 11; ++i) {
        float s = 0.f;
        #pragma unroll
        for (int j = 0; j < 11; ++j) s += win[i * 11 + j];
        g2[i] = pk2(s, s);
    }

    const u64 HC1  = pk2(5e-5f, 5e-5f);     // C1/2
    const u64 HC2  = pk2(4.5e-4f, 4.5e-4f); // C2/2
    const u64 FC1  = pk2(1e-4f, 1e-4f);     // C1
    const u64 FC2  = pk2(9e-4f, 9e-4f);     // C2
    const u64 NEG1 = pk2(-1.f, -1.f);

    // ---- warp-private row fill: cp.async 8B per field ----
    auto fill_row = [&](int p) {
        int slot = p & 7;
        int r_in = r0 - 5 + p;
        float* bx = sbuf[slot][0][w];
        float* by = sbuf[slot][1][w];
        if ((unsigned)r_in < (unsigned)HH) {
            const float* rxg = xb + (size_t)r_in * WW;
            const float* ryg = yb + (size_t)r_in * WW;
            {   // main 64 cols
                unsigned sx = (unsigned)__cvta_generic_to_shared(&bx[8 + 2 * tl]);
                unsigned sy = (unsigned)__cvta_generic_to_shared(&by[8 + 2 * tl]);
                asm volatile("cp.async.ca.shared.global [%0], [%1], 8;" :: "r"(sx), "l"(rxg + cw + 2 * tl) : "memory");
                asm volatile("cp.async.ca.shared.global [%0], [%1], 8;" :: "r"(sy), "l"(ryg + cw + 2 * tl) : "memory");
            }
            if (tl < 4) {
                if (lvalid) {
                    int col = cw - 8 + 2 * tl;
                    unsigned sx = (unsigned)__cvta_generic_to_shared(&bx[2 * tl]);
                    unsigned sy = (unsigned)__cvta_generic_to_shared(&by[2 * tl]);
                    asm volatile("cp.async.ca.shared.global [%0], [%1], 8;" :: "r"(sx), "l"(rxg + col) : "memory");
                    asm volatile("cp.async.ca.shared.global [%0], [%1], 8;" :: "r"(sy), "l"(ryg + col) : "memory");
                }
            } else if (tl < 8) {
                if (rvalid) {
                    int k = tl - 4;
                    int col = cw + 64 + 2 * k;
                    unsigned sx = (unsigned)__cvta_generic_to_shared(&bx[72 + 2 * k]);
                    unsigned sy = (unsigned)__cvta_generic_to_shared(&by[72 + 2 * k]);
                    asm volatile("cp.async.ca.shared.global [%0], [%1], 8;" :: "r"(sx), "l"(rxg + col) : "memory");
                    asm volatile("cp.async.ca.shared.global [%0], [%1], 8;" :: "r"(sy), "l"(ryg + col) : "memory");
                }
            }
        } else {
            // out-of-image row: zero the warp strip (incl. valid halos)
            *(float2*)&bx[8 + 2 * tl] = make_float2(0.f, 0.f);
            *(float2*)&by[8 + 2 * tl] = make_float2(0.f, 0.f);
            if (tl < 4) {
                if (lvalid) {
                    *(float2*)&bx[2 * tl] = make_float2(0.f, 0.f);
                    *(float2*)&by[2 * tl] = make_float2(0.f, 0.f);
                }
            } else if (tl < 8) {
                if (rvalid) {
                    int k = tl - 4;
                    *(float2*)&bx[72 + 2 * k] = make_float2(0.f, 0.f);
                    *(float2*)&by[72 + 2 * k] = make_float2(0.f, 0.f);
                }
            }
        }
    };

    // prologue: prefetch rows 0..DIST-1, one commit group each
    #pragma unroll
    for (int p = 0; p < DIST; ++p) {
        fill_row(p);
        asm volatile("cp.async.commit_group;" ::: "memory");
    }

    // register ring: 11 rows x 4 packed fields (mu_x, mu_y, x^2+y^2, x*y)
    u64 RX[11], RY[11], RS[11], RP[11];
    float acc = 0.f;

    for (int blk = 0; blk < 7; ++blk) {
        #pragma unroll
        for (int ph = 0; ph < 11; ++ph) {
            const int pr = blk * 11 + ph;
            if (pr < NSTAGE) {
                // warp-private pipeline: slot (pr+6)&7 = (pr-2)&7 was consumed
                // by this same warp two iterations ago -> no barrier needed.
                int pf = pr + DIST;
                if (pf < NSTAGE) fill_row(pf);
                asm volatile("cp.async.commit_group;" ::: "memory");
                asm volatile("cp.async.wait_group %0;" :: "n"(DIST) : "memory");
                __syncwarp();   // make warp-mates' staged row visible

                // stage 14 floats per field into registers (aligned float2 loads)
                const float2* xv = (const float2*)sbuf[pr & 7][0][w] + (tl + 1);
                const float2* yv = (const float2*)sbuf[pr & 7][1][w] + (tl + 1);
                float xr[14], yr[14];
                #pragma unroll
                for (int i = 0; i < 7; ++i) {
                    float2 a = xv[i]; xr[2 * i] = a.x; xr[2 * i + 1] = a.y;
                    float2 c = yv[i]; yr[2 * i] = c.x; yr[2 * i + 1] = c.y;
                }

                // horizontal 11-tap conv, packed over column pair (cw+2tl, cw+2tl+1)
                u64 hx = 0, hy = 0, hs = 0, hp = 0;
                #pragma unroll
                for (int j = 0; j < 11; ++j) {
                    u64 ax = pk2(xr[1 + j], xr[2 + j]);
                    u64 ay = pk2(yr[1 + j], yr[2 + j]);
                    hx = f2fma(g2[j], ax, hx);
                    hy = f2fma(g2[j], ay, hy);
                    u64 ss = f2mul(ax, ax);
                    ss = f2fma(ay, ay, ss);
                    hs = f2fma(g2[j], ss, hs);
                    u64 pp = f2mul(ax, ay);
                    hp = f2fma(g2[j], pp, hp);
                }
                RX[ph] = hx; RY[ph] = hy; RS[ph] = hs; RP[ph] = hp;

                // vertical 11-tap conv + SSIM once ring is warm
                if (pr >= 10) {
                    u64 mx = f2mul(g2[0], RX[(ph + 1) % 11]);
                    u64 my = f2mul(g2[0], RY[(ph + 1) % 11]);
                    u64 sp = f2mul(g2[0], RS[(ph + 1) % 11]);
                    u64 sx = f2mul(g2[0], RP[(ph + 1) % 11]);
                    #pragma unroll
                    for (int k = 1; k < 11; ++k) {
                        const int sl = (ph + 1 + k) % 11;
                        mx = f2fma(g2[k], RX[sl], mx);
                        my = f2fma(g2[k], RY[sl], my);
                        sp = f2fma(g2[k], RS[sl], sp);
                        sx = f2fma(g2[k], RP[sl], sx);
                    }
                    u64 mx2 = f2mul(mx, mx);
                    u64 my2 = f2mul(my, my);
                    u64 mxy = f2mul(mx, my);
                    u64 msq = f2add(mx2, my2);
                    u64 vp  = f2fma(msq, NEG1, sp);    // sigma_x^2 + sigma_y^2
                    u64 vxy = f2fma(mxy, NEG1, sx);    // sigma_xy
                    u64 t1  = f2add(mxy, HC1);
                    u64 t2  = f2add(vxy, HC2);
                    u64 num = f2mul(t1, t2);           // ssim = 4*num/den
                    u64 t3  = f2add(msq, FC1);
                    u64 t4  = f2add(vp,  FC2);
                    u64 den = f2mul(t3, t4);
                    float n0, n1, d0, d1;
                    upk2(num, n0, n1);
                    upk2(den, d0, d1);
                    acc += __fdividef(n0, d0) + __fdividef(n1, d1);
                }
            }
        }
    }

    // ---- deterministic per-CTA reduction -> partial ----
    #pragma unroll
    for (int o = 16; o; o >>= 1) acc += __shfl_down_sync(0xFFFFFFFFu, acc, o);
    if (tl == 0) swarp[w] = acc;
    __syncthreads();
    if (t == 0) {
        float s = (swarp[0] + swarp[1]) + (swarp[2] + swarp[3]);
        g_partials[blockIdx.y * (NROWT * NCOLT) + blockIdx.x] = s;
        __threadfence();
        unsigned old = atomicAdd(&g_ticket, 1u);
        s_last = (old == NPART - 1);
    }
    __syncthreads();

    // ---- last CTA: fixed-order final reduction (deterministic) ----
    if (s_last) {
        __threadfence();
        float v = 0.f;
        #pragma unroll
        for (int k = 0; k < NPART / NTHREADS; ++k)
            v += g_partials[t + NTHREADS * k];
        #pragma unroll
        for (int o = 16; o; o >>= 1) v += __shfl_down_sync(0xFFFFFFFFu, v, o);
        __syncthreads();
        if (tl == 0) swarp[w] = v;
        __syncthreads();
        if (t == 0) {
            float s = (swarp[0] + swarp[1]) + (swarp[2] + swarp[3]);
            // accumulated terms were num/4 / den -> scale by 4 / (B*H*W)
            out[0] = s * (4.0f / 16777216.0f);
            g_ticket = 0;   // reset for next graph replay
        }
    }
}

extern "C" void kernel_launch(void* const* d_in, const int* in_sizes, int n_in,
                              void* d_out, int out_size)
{
    const float* x   = (const float*)d_in[0];
    const float* y   = (const float*)d_in[1];
    const float* win = (const float*)d_in[2];
    float* out = (float*)d_out;

    dim3 grid(NROWT * NCOLT, BATCH);   // (16, 64) = 1024 CTAs
    ssim_map_kernel<<<grid, NTHREADS>>>(x, y, win, out);
}